// round 9
// baseline (speedup 1.0000x reference)
#include <cuda_runtime.h>
#include <float.h>
#include <math.h>

// Problem constants (shapes fixed by the dataset)
#define DIM       256
#define MAXB      128
#define TOPK      32
#define CAND_CAP  65536

#define INV_TAU   10.0f     // 1 / 0.1
#define PEN_COEF  0.25f     // BETA / (2*SIGMA^2) = 0.5 / 2
#define SIM_BOUND 10.0f     // max |q.K| / tau  (q, K unit-norm)

#define QG 32               // queries per logits tile
#define CG 64               // candidates per logits chunk
#define NBLK 296            // 2 blocks/SM x 148 SMs -> all resident
#define NTHR 128
#define P_PARTS 8           // selection parts per query
#define EQCAP 2048          // per-part element capacity (fast path)
#define RANKCAP 512         // rank-resolve shortcut limit

// ---------------- scratch (device globals; no allocation allowed) ----------
__device__ unsigned int g_ctr;                       // monotonic epoch counter
__device__ int          g_count;
__device__ int          g_qdone[MAXB];
__device__ float        g_minblk[NBLK][32];
__device__ int          g_cidx[CAND_CAP];
__device__ float        g_cpen[CAND_CAP];
__device__ float        g_qn[MAXB * DIM];
__device__ float        g_logits[(size_t)MAXB * CAND_CAP];           // 32 MB
__device__ unsigned long long g_pk[MAXB][P_PARTS * TOPK];            // staging

// order-preserving float <-> uint (descending float == descending uint)
__device__ __forceinline__ unsigned int f2u_ord(float f) {
    unsigned int u = __float_as_uint(f);
    return (u & 0x80000000u) ? ~u : (u | 0x80000000u);
}
__device__ __forceinline__ float u2f_ord(unsigned int u) {
    return (u & 0x80000000u) ? __uint_as_float(u & 0x7FFFFFFFu)
                             : __uint_as_float(~u);
}
// 64-bit key: value (ordered) high, ~candidate-position low. Distinct keys;
// bigger == better; lower position wins ties.
__device__ __forceinline__ unsigned long long mk_key(float v, int m) {
    return ((unsigned long long)f2u_ord(v) << 32) |
           (unsigned int)(~(unsigned int)m);
}

// epoch grid barrier: every barrier consumes exactly nb tickets globally, so
// it is safe across CUDA-graph replays and across multiple barriers/launch.
__device__ __forceinline__ void grid_barrier(int nb, int tid) {
    __threadfence();
    __syncthreads();
    if (tid == 0) {
        unsigned int ticket = atomicAdd(&g_ctr, 1u);
        unsigned int target = (ticket / (unsigned)nb + 1u) * (unsigned)nb;
        while (atomicAdd(&g_ctr, 0u) < target) __nanosleep(32);
    }
    __syncthreads();
    __threadfence();
}

// Warp-0 register suffix-scan over a 256-bin histogram; finds the unique
// bin t with sfx[t] >= K and sfx[t+1] < K.
__device__ __forceinline__ void warp_cutoff(const unsigned int* h, int K,
                                            int* out, int lane) {
    unsigned int loc[8];
    int b8 = lane * 8;
    #pragma unroll
    for (int k = 0; k < 8; k++) loc[k] = h[b8 + k];
    #pragma unroll
    for (int k = 6; k >= 0; k--) loc[k] += loc[k + 1];
    unsigned int total = loc[0];
    unsigned int val = total;
    #pragma unroll
    for (int off = 1; off < 32; off <<= 1) {
        unsigned int o = __shfl_down_sync(0xFFFFFFFFu, val, off);
        if (lane + off < 32) val += o;
    }
    unsigned int excl = val - total;
    #pragma unroll
    for (int k = 0; k < 8; k++) {
        unsigned int sfx = loc[k] + excl;
        unsigned int abv = (k < 7) ? (loc[k + 1] + excl) : excl;
        if (sfx >= (unsigned)K && abv < (unsigned)K) *out = b8 + k;
    }
}

// ---------------------------------------------------------------------------
// THE kernel: pre -> barrier -> logits -> barrier -> select/merge.
// ---------------------------------------------------------------------------
extern __shared__ float s_dyn[];   // 96 KB: logits tiles / selection buffers

__global__ void __launch_bounds__(NTHR, 2)
k_all(const float* __restrict__ times, const float* __restrict__ qtime,
      const float* __restrict__ query, const float* __restrict__ Kbank,
      const float* __restrict__ Vbank, float* __restrict__ out,
      int N, int B) {
    __shared__ float s[NTHR];
    __shared__ float sth;
    __shared__ float spen[CG];
    __shared__ unsigned long long wink[TOPK];
    __shared__ unsigned long long red[4];
    __shared__ int s_nwin, s_neq[2], s_bin, s_last;
    __shared__ float sv[TOPK];
    __shared__ int   si[TOPK];

    const int tid = threadIdx.x, bid = blockIdx.x;
    const int nb = gridDim.x;
    const int lane = tid & 31, warp = tid >> 5;

    // ================= Phase A: pre =================
    if (bid == 0) {
        if (tid == 0) g_count = 0;
        if (tid < MAXB) g_qdone[tid] = 0;
    }

    // --- query L2 normalization (matches F.normalize, eps=1e-12) ---
    if (bid < B) {
        float v0 = query[bid * DIM + tid];
        float v1 = query[bid * DIM + tid + 128];
        float ss = v0 * v0 + v1 * v1;
        #pragma unroll
        for (int off = 16; off > 0; off >>= 1)
            ss += __shfl_xor_sync(0xFFFFFFFFu, ss, off);
        if (lane == 0) s[warp] = ss;
        __syncthreads();
        if (tid == 0)
            s[0] = fmaxf(sqrtf(s[0] + s[1] + s[2] + s[3]), 1e-12f);
        __syncthreads();
        float nrm = s[0];
        g_qn[bid * DIM + tid]       = v0 / nrm;
        g_qn[bid * DIM + tid + 128] = v1 / nrm;
        __syncthreads();
    }

    const float qt = qtime[0];
    const int n4 = N >> 2;
    const float4* t4 = (const float4*)times;

    // --- pass 1 (sampled): one float4 per thread, per-residue minima ---
    // Residue groups: row set {4*vv+j : vv mod 32 == g} are disjoint across g,
    // so the 32 group minima sit at 32 distinct rows ->
    // max(group minima) >= 32nd-smallest penalty. Sound for any subset.
    {
        int vv = bid * NTHR + tid;            // vv & 31 == tid & 31
        float pmin = FLT_MAX;
        if (vv < n4) {
            float4 tv = t4[vv];
            float d0 = qt - tv.x, d1 = qt - tv.y, d2 = qt - tv.z, d3 = qt - tv.w;
            pmin = fminf(fminf(PEN_COEF * d0 * d0, PEN_COEF * d1 * d1),
                         fminf(PEN_COEF * d2 * d2, PEN_COEF * d3 * d3));
        }
        s[tid] = pmin;
        __syncthreads();
        if (tid < 32) {
            float m = fminf(fminf(s[tid], s[tid + 32]),
                            fminf(s[tid + 64], s[tid + 96]));
            g_minblk[bid][tid] = m;
        }
    }

    grid_barrier(nb, tid);

    // --- threshold: per-residue min over blocks, then max over residues ---
    {
        int r = tid & 31, sub = tid >> 5;     // 4 threads per residue
        float m = FLT_MAX;
        for (int i = sub; i < nb; i += 4) m = fminf(m, g_minblk[i][r]);
        s[tid] = m;
        __syncthreads();
        if (tid < 32) {
            float mm = fminf(fminf(s[tid], s[tid + 32]),
                             fminf(s[tid + 64], s[tid + 96]));
            s[tid] = mm;
        }
        __syncthreads();
        if (tid == 0) {
            float mx = -FLT_MAX;
            #pragma unroll
            for (int g = 0; g < 32; g++) mx = fmaxf(mx, s[g]);
            sth = mx + 2.0f * SIM_BOUND + 4.0f;   // sound bound + fp margin
        }
        __syncthreads();
    }
    const float thresh = sth;

    // --- pass 2 (full): float4 + warp-aggregated compaction ---
    for (int vv0 = bid * NTHR; vv0 < n4; vv0 += nb * NTHR) {
        int vv = vv0 + tid;
        float pv[4];
        int cc[4] = {0, 0, 0, 0};
        int loc = 0;
        if (vv < n4) {
            float4 tv = t4[vv];
            float d0 = qt - tv.x, d1 = qt - tv.y, d2 = qt - tv.z, d3 = qt - tv.w;
            pv[0] = PEN_COEF * d0 * d0; pv[1] = PEN_COEF * d1 * d1;
            pv[2] = PEN_COEF * d2 * d2; pv[3] = PEN_COEF * d3 * d3;
            #pragma unroll
            for (int j = 0; j < 4; j++) { cc[j] = pv[j] <= thresh; loc += cc[j]; }
        }
        // warp-inclusive scan of loc; ONE atomic per warp
        int pre = loc;
        #pragma unroll
        for (int off = 1; off < 32; off <<= 1) {
            int t = __shfl_up_sync(0xFFFFFFFFu, pre, off);
            if (lane >= off) pre += t;
        }
        int wtotal = __shfl_sync(0xFFFFFFFFu, pre, 31);
        int wbase = 0;
        if (wtotal) {
            if (lane == 31) wbase = atomicAdd(&g_count, wtotal);
            wbase = __shfl_sync(0xFFFFFFFFu, wbase, 31);
            int pos = wbase + pre - loc;
            int nbase = vv * 4;
            #pragma unroll
            for (int j = 0; j < 4; j++) {
                if (cc[j]) {
                    if (pos < CAND_CAP) { g_cidx[pos] = nbase + j; g_cpen[pos] = pv[j]; }
                    pos++;
                }
            }
        }
    }
    {   // scalar tail (N % 4)
        int rem = N - n4 * 4;
        if (bid == 0 && tid < rem) {
            int n = n4 * 4 + tid;
            float dt = qt - times[n];
            float p = PEN_COEF * dt * dt;
            if (p <= thresh) {
                int pos = atomicAdd(&g_count, 1);
                if (pos < CAND_CAP) { g_cidx[pos] = n; g_cpen[pos] = p; }
            }
        }
    }

    grid_barrier(nb, tid);

    // ================= Phase B: logits =================
    const int cnt = min(g_count, CAND_CAP);
    {
        float* qs = s_dyn;             // [d*QG + q]
        float* kv = s_dyn + DIM * QG;  // [d*CG + c]
        int ngrp = (B + QG - 1) / QG;
        int xdim = nb / ngrp;          // chunk-stride blocks per group (74)
        int grp = bid / xdim, x = bid - grp * xdim;

        if (cnt > 0 && grp < ngrp) {
            const float4* qn4 = (const float4*)g_qn;
            const float4* K4  = (const float4*)Kbank;

            // load 32 queries transposed
            {
                int q = tid & 31, d4b = tid >> 5;
                int b = grp * QG + q;
                #pragma unroll
                for (int i = 0; i < 16; i++) {
                    int d4 = d4b + 4 * i;
                    float4 v = (b < B) ? qn4[(size_t)b * (DIM / 4) + d4]
                                       : make_float4(0.f, 0.f, 0.f, 0.f);
                    qs[(d4 * 4 + 0) * QG + q] = v.x;
                    qs[(d4 * 4 + 1) * QG + q] = v.y;
                    qs[(d4 * 4 + 2) * QG + q] = v.z;
                    qs[(d4 * 4 + 3) * QG + q] = v.w;
                }
            }

            int cq = tid & 15, qq = tid >> 4;
            int c0 = cq * 4, q0 = qq * 4;

            for (int m0 = x * CG; m0 < cnt; m0 += xdim * CG) {
                __syncthreads();
                {
                    int c = tid & 63, d4b = tid >> 6;
                    int row = g_cidx[min(m0 + c, cnt - 1)];
                    #pragma unroll
                    for (int i = 0; i < 32; i++) {
                        int d4 = d4b + 2 * i;
                        float4 v = K4[(size_t)row * (DIM / 4) + d4];
                        kv[(d4 * 4 + 0) * CG + c] = v.x;
                        kv[(d4 * 4 + 1) * CG + c] = v.y;
                        kv[(d4 * 4 + 2) * CG + c] = v.z;
                        kv[(d4 * 4 + 3) * CG + c] = v.w;
                    }
                }
                if (tid < CG) spen[tid] = g_cpen[min(m0 + tid, cnt - 1)];
                __syncthreads();

                float acc[16];
                #pragma unroll
                for (int i = 0; i < 16; i++) acc[i] = 0.0f;

                #pragma unroll 4
                for (int d = 0; d < DIM; d++) {
                    float4 kf = *(const float4*)&kv[d * CG + c0];
                    float4 qf = *(const float4*)&qs[d * QG + q0];
                    acc[0]  += qf.x * kf.x;  acc[1]  += qf.x * kf.y;
                    acc[2]  += qf.x * kf.z;  acc[3]  += qf.x * kf.w;
                    acc[4]  += qf.y * kf.x;  acc[5]  += qf.y * kf.y;
                    acc[6]  += qf.y * kf.z;  acc[7]  += qf.y * kf.w;
                    acc[8]  += qf.z * kf.x;  acc[9]  += qf.z * kf.y;
                    acc[10] += qf.z * kf.z;  acc[11] += qf.z * kf.w;
                    acc[12] += qf.w * kf.x;  acc[13] += qf.w * kf.y;
                    acc[14] += qf.w * kf.z;  acc[15] += qf.w * kf.w;
                }

                float p0 = spen[c0 + 0], p1 = spen[c0 + 1];
                float p2 = spen[c0 + 2], p3 = spen[c0 + 3];
                bool full = (m0 + c0 + 3) < cnt;
                #pragma unroll
                for (int qj = 0; qj < 4; qj++) {
                    int b = grp * QG + q0 + qj;
                    if (b >= B) break;
                    float* dst = g_logits + (size_t)b * CAND_CAP + m0 + c0;
                    float4 v;
                    v.x = acc[qj * 4 + 0] * INV_TAU - p0;
                    v.y = acc[qj * 4 + 1] * INV_TAU - p1;
                    v.z = acc[qj * 4 + 2] * INV_TAU - p2;
                    v.w = acc[qj * 4 + 3] * INV_TAU - p3;
                    if (full) {
                        *(float4*)dst = v;
                    } else {
                        float vv[4] = {v.x, v.y, v.z, v.w};
                        for (int cj = 0; cj < 4; cj++)
                            if (m0 + c0 + cj < cnt) dst[cj] = vv[cj];
                    }
                }
            }
        }
    }

    grid_barrier(nb, tid);

    // ================= Phase C: select + merge =================
    unsigned long long* keys = (unsigned long long*)s_dyn;            // 16 KB
    unsigned short* eqi0 = (unsigned short*)(s_dyn + 4096);           //  4 KB
    unsigned short* eqi1 = (unsigned short*)(s_dyn + 5120);           //  4 KB
    unsigned int*   h0   = (unsigned int*)(s_dyn + 6144);             //  1 KB
    unsigned short* eqi[2] = {eqi0, eqi1};

    for (int t = bid; t < P_PARTS * B; t += nb) {
        int b = t >> 3, p = t & (P_PARTS - 1);
        float* grow = g_logits + (size_t)b * CAND_CAP;

        int base = (int)(((long long)cnt * p) / P_PARTS);
        int end  = (int)(((long long)cnt * (p + 1)) / P_PARTS);
        int np = end - base;
        int selk = min(TOPK, np);

        __syncthreads();                      // smem reuse across tasks
        if (tid == 0) { s_nwin = 0; s_neq[0] = 0; s_neq[1] = 0; }
        if (tid < 128) { h0[tid] = 0u; h0[tid + 128] = 0u; }
        __syncthreads();

        if (np > 0 && np <= EQCAP) {
            // single gmem pass: stage keys + histogram byte 7
            for (int i = tid; i < np; i += NTHR) {
                unsigned long long key = mk_key(grow[base + i], base + i);
                keys[i] = key;
                unsigned int bin = (unsigned int)(key >> 56);
                unsigned int am = __activemask();
                unsigned int mk = __match_any_sync(am, bin);
                if (lane == __ffs(mk) - 1) atomicAdd(&h0[bin], __popc(mk));
            }
            __syncthreads();
            if (warp == 0) warp_cutoff(h0, selk, &s_bin, lane);
            __syncthreads();
            int bs = s_bin;
            for (int i = tid; i < np; i += NTHR) {
                int byt = (int)(keys[i] >> 56);
                if (byt > bs) {
                    int q = atomicAdd(&s_nwin, 1);
                    wink[q] = keys[i];
                } else if (byt == bs) {
                    int q = atomicAdd(&s_neq[0], 1);
                    eqi[0][q] = (unsigned short)i;
                }
            }
            __syncthreads();

            // resolve equals: rank shortcut, deeper radix only if large
            int cur = 0;
            for (int lvl = 1; lvl < 8; lvl++) {
                int ne = s_neq[cur];
                int krem = selk - s_nwin;
                if (krem <= 0) break;
                if (ne == krem) {
                    for (int i = tid; i < ne; i += NTHR) {
                        int q = atomicAdd(&s_nwin, 1);
                        wink[q] = keys[eqi[cur][i]];
                    }
                    break;
                }
                if (ne <= RANKCAP) {
                    for (int i = tid; i < ne; i += NTHR) {
                        unsigned long long key = keys[eqi[cur][i]];
                        int rank = 0;
                        for (int j = 0; j < ne; j++)
                            rank += (keys[eqi[cur][j]] > key) ? 1 : 0;
                        if (rank < krem) {
                            int q = atomicAdd(&s_nwin, 1);
                            wink[q] = key;
                        }
                    }
                    break;
                }
                int sh = 56 - 8 * lvl;
                __syncthreads();
                if (tid < 128) { h0[tid] = 0u; h0[tid + 128] = 0u; }
                if (tid == 0) s_neq[cur ^ 1] = 0;
                __syncthreads();
                for (int i = tid; i < ne; i += NTHR) {
                    unsigned int bin = (unsigned int)((keys[eqi[cur][i]] >> sh) & 0xFFull);
                    unsigned int am = __activemask();
                    unsigned int mk = __match_any_sync(am, bin);
                    if (lane == __ffs(mk) - 1) atomicAdd(&h0[bin], __popc(mk));
                }
                __syncthreads();
                if (warp == 0) warp_cutoff(h0, krem, &s_bin, lane);
                __syncthreads();
                int bsl = s_bin;
                for (int i = tid; i < ne; i += NTHR) {
                    unsigned short ix = eqi[cur][i];
                    int byt = (int)((keys[ix] >> sh) & 0xFFull);
                    if (byt > bsl) {
                        int q = atomicAdd(&s_nwin, 1);
                        wink[q] = keys[ix];
                    } else if (byt == bsl) {
                        int q = atomicAdd(&s_neq[cur ^ 1], 1);
                        eqi[cur ^ 1][q] = ix;
                    }
                }
                __syncthreads();
                cur ^= 1;
            }
        } else if (np > EQCAP) {
            // fallback (adversarial cnt only): destructive argmax rounds
            for (int k = 0; k < selk; k++) {
                unsigned long long best = 0ull;
                for (int m = base + tid; m < end; m += NTHR) {
                    unsigned long long key = mk_key(grow[m], m);
                    if (key > best) best = key;
                }
                #pragma unroll
                for (int off = 16; off > 0; off >>= 1) {
                    unsigned long long o = __shfl_down_sync(0xFFFFFFFFu, best, off);
                    if (o > best) best = o;
                }
                if (lane == 0) red[warp] = best;
                __syncthreads();
                if (tid == 0) {
                    unsigned long long bb = red[0];
                    #pragma unroll
                    for (int w = 1; w < 4; w++) if (red[w] > bb) bb = red[w];
                    wink[k] = bb;
                    int m = (int)(~(unsigned int)(bb & 0xFFFFFFFFull));
                    grow[m] = -FLT_MAX;       // part range is task-private
                }
                __syncthreads();
            }
        }
        __syncthreads();

        // write staging (pad with tiny distinct keys; real keys >= 2^32)
        if (tid < TOPK) {
            unsigned long long key = (tid < selk)
                ? wink[tid]
                : (unsigned long long)(p * TOPK + tid + 1);
            g_pk[b][p * TOPK + tid] = key;
        }
        __syncthreads();

        // last finished part for this query does the merge
        if (tid == 0) {
            __threadfence();
            s_last = (atomicAdd(&g_qdone[b], 1) == P_PARTS - 1) ? 1 : 0;
        }
        __syncthreads();
        if (!s_last) continue;
        __threadfence();   // acquire other parts' g_pk writes

        unsigned long long k0 = g_pk[b][tid];
        unsigned long long k1 = g_pk[b][tid + 128];
        __syncthreads();
        keys[tid] = k0; keys[tid + 128] = k1;
        __syncthreads();
        int r0 = 0, r1 = 0;
        #pragma unroll 8
        for (int j = 0; j < P_PARTS * TOPK; j++) {
            unsigned long long kj = keys[j];
            r0 += (kj > k0) ? 1 : 0;
            r1 += (kj > k1) ? 1 : 0;
        }
        if (r0 < TOPK) {
            sv[r0] = u2f_ord((unsigned int)(k0 >> 32));
            si[r0] = (int)(~(unsigned int)(k0 & 0xFFFFFFFFull));
        }
        if (r1 < TOPK) {
            sv[r1] = u2f_ord((unsigned int)(k1 >> 32));
            si[r1] = (int)(~(unsigned int)(k1 & 0xFFFFFFFFull));
        }
        __syncthreads();

        if (tid < TOPK) si[tid] = g_cidx[si[tid]];
        __syncthreads();

        if (tid < 32) {
            float v = sv[tid];
            float mx = v;
            #pragma unroll
            for (int off = 16; off > 0; off >>= 1)
                mx = fmaxf(mx, __shfl_xor_sync(0xFFFFFFFFu, mx, off));
            float e = expf(v - mx);
            float ssum = e;
            #pragma unroll
            for (int off = 16; off > 0; off >>= 1)
                ssum += __shfl_xor_sync(0xFFFFFFFFu, ssum, off);
            sv[tid] = e / ssum;
        }
        __syncthreads();

        float a0 = 0.0f, a1 = 0.0f;
        #pragma unroll
        for (int k = 0; k < TOPK; k++) {
            const float* vr = Vbank + (size_t)si[k] * DIM;
            float w = sv[k];
            a0 += w * vr[tid];
            a1 += w * vr[tid + 128];
        }
        out[b * DIM + tid]       = a0;
        out[b * DIM + tid + 128] = a1;
    }
}

// ---------------------------------------------------------------------------
extern "C" void kernel_launch(void* const* d_in, const int* in_sizes, int n_in,
                              void* d_out, int out_size) {
    const float* query = (const float*)d_in[0];
    const float* Kbank = (const float*)d_in[1];
    const float* Vbank = (const float*)d_in[2];
    const float* times = (const float*)d_in[3];
    const float* qtime = (const float*)d_in[4];
    float* out = (float*)d_out;

    int B = in_sizes[0] / DIM;
    int N = in_sizes[3];

    int smem = (DIM * QG + DIM * CG) * (int)sizeof(float);  // 96 KB
    cudaFuncSetAttribute(k_all, cudaFuncAttributeMaxDynamicSharedMemorySize,
                         smem);

    k_all<<<NBLK, NTHR, smem>>>(times, qtime, query, Kbank, Vbank, out, N, B);
}

// round 10
// speedup vs baseline: 1.4331x; 1.4331x over previous
#include <cuda_runtime.h>
#include <float.h>
#include <math.h>

// Problem constants (shapes fixed by the dataset)
#define DIM       256
#define MAXB      128
#define TOPK      32
#define CAND_CAP  65536

#define INV_TAU   10.0f     // 1 / 0.1
#define PEN_COEF  0.25f     // BETA / (2*SIGMA^2) = 0.5 / 2
#define SIM_BOUND 10.0f     // max |q.K| / tau  (q, K unit-norm)

#define QG 32               // queries per logits tile
#define CG 64               // candidates per logits chunk
#define DH 128              // depth half (d-split 2)
#define LX 111              // logits x-blocks (3/SM * 148 / 4 groups)
#define PRE_BLOCKS 148
#define P_PARTS 8           // selection parts per query
#define EQCAP 2048          // per-part element capacity (fast path)
#define RANKCAP 512         // rank-resolve shortcut limit

// ---------------- scratch (device globals; no allocation allowed) ----------
__device__ unsigned int g_ctr;                       // monotonic epoch counter
__device__ int          g_count;
__device__ int          g_qdone[MAXB];
__device__ float        g_minblk[PRE_BLOCKS][32];
__device__ int          g_cidx[CAND_CAP];
__device__ float        g_cpen[CAND_CAP];
__device__ float        g_qn[MAXB * DIM];
__device__ float        g_logh[2][(size_t)MAXB * CAND_CAP];   // 2 x 32 MB halves
__device__ unsigned long long g_pk[MAXB][P_PARTS * TOPK];     // staging

// order-preserving float <-> uint (descending float == descending uint)
__device__ __forceinline__ unsigned int f2u_ord(float f) {
    unsigned int u = __float_as_uint(f);
    return (u & 0x80000000u) ? ~u : (u | 0x80000000u);
}
__device__ __forceinline__ float u2f_ord(unsigned int u) {
    return (u & 0x80000000u) ? __uint_as_float(u & 0x7FFFFFFFu)
                             : __uint_as_float(~u);
}
// 64-bit key: value (ordered) high, ~candidate-position low. Distinct keys;
// bigger == better; lower position wins ties.
__device__ __forceinline__ unsigned long long mk_key(float v, int m) {
    return ((unsigned long long)f2u_ord(v) << 32) |
           (unsigned int)(~(unsigned int)m);
}

// ---------------------------------------------------------------------------
// Kernel 1: reset + query L2-norm + sampled per-residue penalty minima +
// monotonic grid barrier + threshold + warp-aggregated compaction.
// Grid = 148 x 1024 (all resident -> spin barrier safe).
// Threshold soundness: rows partitioned into 32 disjoint residue groups by
// (n mod 32); the 32 per-group minima sit at 32 DISTINCT rows, so
// max(group minima) >= 32nd-smallest penalty over the sampled subset >= ...
// sampling only loosens the bound. thresh = bound + 2*SIM_BOUND + margin
// never drops a true top-32 row of any query; guarantees cnt >= 32.
// ---------------------------------------------------------------------------
__global__ void __launch_bounds__(1024) k_pre(const float* __restrict__ times,
                                              const float* __restrict__ qtime,
                                              const float* __restrict__ query,
                                              int N, int B) {
    __shared__ float s[1024];
    __shared__ float sth;
    int tid = threadIdx.x, bid = blockIdx.x;
    int nb = gridDim.x;
    int lane = tid & 31;

    // --- per-launch resets (ordered before barrier by threadfence) ---
    if (bid == 0) {
        if (tid == 0) g_count = 0;
        if (tid < MAXB) g_qdone[tid] = 0;
    }

    // --- query L2 normalization (matches F.normalize, eps=1e-12) ---
    float v = 0.0f;
    if (bid < B && tid < DIM) v = query[bid * DIM + tid];
    {
        float ss = v * v;
        #pragma unroll
        for (int off = 16; off > 0; off >>= 1)
            ss += __shfl_xor_sync(0xFFFFFFFFu, ss, off);
        if (lane == 0) s[tid >> 5] = ss;
        __syncthreads();
        if (tid == 0) {
            float t = 0.0f;
            #pragma unroll
            for (int w = 0; w < 8; w++) t += s[w];
            s[0] = fmaxf(sqrtf(t), 1e-12f);
        }
        __syncthreads();
        float nrm = s[0];
        if (bid < B && tid < DIM) g_qn[bid * DIM + tid] = v / nrm;
        __syncthreads();                              // s reused below
    }

    float qt = qtime[0];

    // --- pass 1 (sampled): ONE load per thread, per-residue minima ---
    {
        int n = bid * 1024 + tid;
        float p = FLT_MAX;
        if (n < N) { float dt = qt - times[n]; p = PEN_COEF * dt * dt; }
        s[tid] = p;
        __syncthreads();
        #pragma unroll
        for (int st = 512; st >= 32; st >>= 1) {      // offsets % 32 == 0
            if (tid < st) s[tid] = fminf(s[tid], s[tid + st]);
            __syncthreads();
        }
        if (tid < 32) g_minblk[bid][tid] = s[tid];
    }
    __threadfence();
    __syncthreads();

    // --- monotonic grid barrier (graph-replay safe) ---
    if (tid == 0) {
        unsigned int ticket = atomicAdd(&g_ctr, 1u);
        unsigned int target = (ticket / nb + 1u) * nb;
        while (atomicAdd(&g_ctr, 0u) < target) __nanosleep(32);
        __threadfence();
    }
    __syncthreads();

    // --- threshold: per-residue min over blocks, then max over residues ---
    {
        int r = tid & 31, sub = tid >> 5;
        float m = FLT_MAX;
        for (int i = sub; i < nb; i += 32) m = fminf(m, g_minblk[i][r]);
        s[tid] = m;
        __syncthreads();
        #pragma unroll
        for (int st = 512; st >= 32; st >>= 1) {
            if (tid < st) s[tid] = fminf(s[tid], s[tid + st]);
            __syncthreads();
        }
        if (tid == 0) {
            float mx = -FLT_MAX;
            #pragma unroll
            for (int g = 0; g < 32; g++) mx = fmaxf(mx, s[g]);
            sth = mx + 2.0f * SIM_BOUND + 4.0f;       // sound bound + fp margin
        }
        __syncthreads();
    }
    float thresh = sth;

    // --- pass 2 (full): float4 + warp-aggregated compaction ---
    const float4* t4 = (const float4*)times;
    int n4 = N >> 2;
    for (int vv0 = bid * 1024; vv0 < n4; vv0 += nb * 1024) {
        int vv = vv0 + tid;
        float pv[4];
        int cc[4] = {0, 0, 0, 0};
        int loc = 0;
        if (vv < n4) {
            float4 tv = t4[vv];
            float d0 = qt - tv.x, d1 = qt - tv.y, d2 = qt - tv.z, d3 = qt - tv.w;
            pv[0] = PEN_COEF * d0 * d0; pv[1] = PEN_COEF * d1 * d1;
            pv[2] = PEN_COEF * d2 * d2; pv[3] = PEN_COEF * d3 * d3;
            #pragma unroll
            for (int j = 0; j < 4; j++) { cc[j] = pv[j] <= thresh; loc += cc[j]; }
        }
        int pre = loc;                 // warp-inclusive scan; ONE atomic/warp
        #pragma unroll
        for (int off = 1; off < 32; off <<= 1) {
            int t = __shfl_up_sync(0xFFFFFFFFu, pre, off);
            if (lane >= off) pre += t;
        }
        int wtotal = __shfl_sync(0xFFFFFFFFu, pre, 31);
        if (wtotal) {
            int wbase = 0;
            if (lane == 31) wbase = atomicAdd(&g_count, wtotal);
            wbase = __shfl_sync(0xFFFFFFFFu, wbase, 31);
            int pos = wbase + pre - loc;
            int nbase = vv * 4;
            #pragma unroll
            for (int j = 0; j < 4; j++) {
                if (cc[j]) {
                    if (pos < CAND_CAP) { g_cidx[pos] = nbase + j; g_cpen[pos] = pv[j]; }
                    pos++;
                }
            }
        }
    }
    {   // scalar tail (N % 4)
        int rem = N - n4 * 4;
        if (bid == 0 && tid < rem) {
            int n = n4 * 4 + tid;
            float dt = qt - times[n];
            float p = PEN_COEF * dt * dt;
            if (p <= thresh) {
                int pos = atomicAdd(&g_count, 1);
                if (pos < CAND_CAP) { g_cidx[pos] = n; g_cpen[pos] = p; }
            }
        }
    }
}

// ---------------------------------------------------------------------------
// Kernel 2: exact fp32 partial logits, d-split 2.
// Grid (LX, ngrp), 128 threads, 64 KB dyn smem -> 3 blocks/SM. Tasks per
// query group = 2*nchunks (chunk x depth-half); strided over LX blocks for
// ~1.3x imbalance instead of ~1.9x. Stores RAW half-dots; k_sel combines
// (a + b) * INV_TAU - pen (2-addend fp add is order-invariant).
// ---------------------------------------------------------------------------
extern __shared__ float s_dyn[];   // qs[DIM*QG] (32 KB) then kv[DH*CG] (32 KB)

__global__ void __launch_bounds__(128, 3)
k_logits(const float* __restrict__ Kbank, int B) {
    float* qs = s_dyn;             // [d*QG + q], full depth
    float* kv = s_dyn + DIM * QG;  // [dd*CG + c], half depth

    int tid = threadIdx.x;
    int grp = blockIdx.y;
    int cnt = min(g_count, CAND_CAP);
    if (cnt <= 0) return;
    int nch = (cnt + CG - 1) / CG;

    const float4* qn4 = (const float4*)g_qn;
    const float4* K4  = (const float4*)Kbank;

    // ---- load 32 queries transposed (full 256 d) ----
    {
        int q = tid & 31, d4b = tid >> 5;
        int b = grp * QG + q;
        #pragma unroll
        for (int i = 0; i < 16; i++) {
            int d4 = d4b + 4 * i;
            float4 v = (b < B) ? qn4[(size_t)b * (DIM / 4) + d4]
                               : make_float4(0.f, 0.f, 0.f, 0.f);
            qs[(d4 * 4 + 0) * QG + q] = v.x;
            qs[(d4 * 4 + 1) * QG + q] = v.y;
            qs[(d4 * 4 + 2) * QG + q] = v.z;
            qs[(d4 * 4 + 3) * QG + q] = v.w;
        }
    }

    int cq = tid & 15, qq = tid >> 4;
    int c0 = cq * 4, q0 = qq * 4;

    for (int t = blockIdx.x; t < 2 * nch; t += gridDim.x) {
        int ch = t >> 1, h = t & 1;
        int m0 = ch * CG;
        int hb = h * DH;

        __syncthreads();   // protect kv from previous task's readers

        // ---- load 64 candidate K rows, half depth, transposed ----
        {
            int c = tid & 63, d4b = tid >> 6;      // d4b in 0..1
            int row = g_cidx[min(m0 + c, cnt - 1)];
            const float4* kr = K4 + (size_t)row * (DIM / 4) + hb / 4;
            #pragma unroll
            for (int i = 0; i < 16; i++) {
                int d4 = d4b + 2 * i;              // 0..31 local
                float4 v = kr[d4];
                kv[(d4 * 4 + 0) * CG + c] = v.x;
                kv[(d4 * 4 + 1) * CG + c] = v.y;
                kv[(d4 * 4 + 2) * CG + c] = v.z;
                kv[(d4 * 4 + 3) * CG + c] = v.w;
            }
        }
        __syncthreads();

        float acc[16];
        #pragma unroll
        for (int i = 0; i < 16; i++) acc[i] = 0.0f;

        #pragma unroll 4
        for (int dd = 0; dd < DH; dd++) {
            float4 kf = *(const float4*)&kv[dd * CG + c0];
            float4 qf = *(const float4*)&qs[(hb + dd) * QG + q0];
            acc[0]  += qf.x * kf.x;  acc[1]  += qf.x * kf.y;
            acc[2]  += qf.x * kf.z;  acc[3]  += qf.x * kf.w;
            acc[4]  += qf.y * kf.x;  acc[5]  += qf.y * kf.y;
            acc[6]  += qf.y * kf.z;  acc[7]  += qf.y * kf.w;
            acc[8]  += qf.z * kf.x;  acc[9]  += qf.z * kf.y;
            acc[10] += qf.z * kf.z;  acc[11] += qf.z * kf.w;
            acc[12] += qf.w * kf.x;  acc[13] += qf.w * kf.y;
            acc[14] += qf.w * kf.z;  acc[15] += qf.w * kf.w;
        }

        bool full = (m0 + c0 + 3) < cnt;
        #pragma unroll
        for (int qj = 0; qj < 4; qj++) {
            int b = grp * QG + q0 + qj;
            if (b >= B) break;
            float* dst = g_logh[h] + (size_t)b * CAND_CAP + m0 + c0;
            float4 v = make_float4(acc[qj * 4 + 0], acc[qj * 4 + 1],
                                   acc[qj * 4 + 2], acc[qj * 4 + 3]);
            if (full) {
                *(float4*)dst = v;
            } else {
                float vv[4] = {v.x, v.y, v.z, v.w};
                for (int cj = 0; cj < 4; cj++)
                    if (m0 + c0 + cj < cnt) dst[cj] = vv[cj];
            }
        }
    }
}

// ---------------------------------------------------------------------------
// Warp-0 register suffix-scan over a 256-bin histogram.
// ---------------------------------------------------------------------------
__device__ __forceinline__ void warp_cutoff(const unsigned int* h, int K,
                                            int* out, int lane) {
    unsigned int loc[8];
    int b8 = lane * 8;
    #pragma unroll
    for (int k = 0; k < 8; k++) loc[k] = h[b8 + k];
    #pragma unroll
    for (int k = 6; k >= 0; k--) loc[k] += loc[k + 1];
    unsigned int total = loc[0];
    unsigned int val = total;
    #pragma unroll
    for (int off = 1; off < 32; off <<= 1) {
        unsigned int o = __shfl_down_sync(0xFFFFFFFFu, val, off);
        if (lane + off < 32) val += o;
    }
    unsigned int excl = val - total;
    #pragma unroll
    for (int k = 0; k < 8; k++) {
        unsigned int sfx = loc[k] + excl;
        unsigned int abv = (k < 7) ? (loc[k + 1] + excl) : excl;
        if (sfx >= (unsigned)K && abv < (unsigned)K) *out = b8 + k;
    }
}

// combined logit value at candidate position m for query row pointers
__device__ __forceinline__ float logit_at(const float* ga, const float* gb,
                                          int m) {
    return (ga[m] + gb[m]) * INV_TAU - g_cpen[m];
}

// ---------------------------------------------------------------------------
// Kernel 3: per (query, part) EXACT top-32 via radix level 0 + rank-resolve;
// LAST part block per query merges 256 staged keys by rank, softmaxes,
// gathers V. Grid (P_PARTS, B), 256 threads.
// ---------------------------------------------------------------------------
__global__ void __launch_bounds__(256) k_sel(const float* __restrict__ Vbank,
                                             float* __restrict__ out, int B) {
    __shared__ unsigned long long keys[EQCAP];
    __shared__ unsigned short eqi[2][EQCAP];
    __shared__ unsigned int h0[256];
    __shared__ unsigned long long wink[TOPK];
    __shared__ unsigned long long red[8];
    __shared__ int s_nwin, s_neq[2], s_b, s_last;
    __shared__ float sv[TOPK];
    __shared__ int   si[TOPK];

    int p = blockIdx.x, b = blockIdx.y;
    int tid = threadIdx.x, lane = tid & 31, warp = tid >> 5;
    int cnt = min(g_count, CAND_CAP);
    const float* ga = g_logh[0] + (size_t)b * CAND_CAP;
    const float* gb = g_logh[1] + (size_t)b * CAND_CAP;

    int base = (int)(((long long)cnt * p) / P_PARTS);
    int end  = (int)(((long long)cnt * (p + 1)) / P_PARTS);
    int np = end - base;
    int selk = min(TOPK, np);

    if (tid == 0) { s_nwin = 0; s_neq[0] = 0; s_neq[1] = 0; }
    h0[tid] = 0u;
    __syncthreads();

    if (np > 0 && np <= EQCAP) {
        // ---- single gmem pass: combine halves, stage keys, histogram ----
        for (int i = tid; i < np; i += 256) {
            float v = logit_at(ga, gb, base + i);
            unsigned long long key = mk_key(v, base + i);
            keys[i] = key;
            unsigned int bin = (unsigned int)(key >> 56);
            unsigned int am = __activemask();
            unsigned int mk = __match_any_sync(am, bin);
            if (lane == __ffs(mk) - 1) atomicAdd(&h0[bin], __popc(mk));
        }
        __syncthreads();
        if (warp == 0) warp_cutoff(h0, selk, &s_b, lane);
        __syncthreads();
        int bs = s_b;
        for (int i = tid; i < np; i += 256) {
            int byt = (int)(keys[i] >> 56);
            if (byt > bs) {
                int q = atomicAdd(&s_nwin, 1);
                wink[q] = keys[i];
            } else if (byt == bs) {
                int q = atomicAdd(&s_neq[0], 1);
                eqi[0][q] = (unsigned short)i;
            }
        }
        __syncthreads();

        // ---- resolve equals: rank shortcut, deeper radix only if large ----
        int cur = 0;
        for (int lvl = 1; lvl < 8; lvl++) {
            int ne = s_neq[cur];
            int krem = selk - s_nwin;
            if (krem <= 0) break;
            if (ne == krem) {
                for (int i = tid; i < ne; i += 256) {
                    int q = atomicAdd(&s_nwin, 1);
                    wink[q] = keys[eqi[cur][i]];
                }
                break;
            }
            if (ne <= RANKCAP) {
                for (int i = tid; i < ne; i += 256) {
                    unsigned long long key = keys[eqi[cur][i]];
                    int rank = 0;
                    for (int j = 0; j < ne; j++)
                        rank += (keys[eqi[cur][j]] > key) ? 1 : 0;
                    if (rank < krem) {
                        int q = atomicAdd(&s_nwin, 1);
                        wink[q] = key;
                    }
                }
                break;
            }
            int sh = 56 - 8 * lvl;
            h0[tid] = 0u;
            if (tid == 0) s_neq[cur ^ 1] = 0;
            __syncthreads();
            for (int i = tid; i < ne; i += 256) {
                unsigned int bin = (unsigned int)((keys[eqi[cur][i]] >> sh) & 0xFFull);
                unsigned int am = __activemask();
                unsigned int mk = __match_any_sync(am, bin);
                if (lane == __ffs(mk) - 1) atomicAdd(&h0[bin], __popc(mk));
            }
            __syncthreads();
            if (warp == 0) warp_cutoff(h0, krem, &s_b, lane);
            __syncthreads();
            int bsl = s_b;
            for (int i = tid; i < ne; i += 256) {
                unsigned short ix = eqi[cur][i];
                int byt = (int)((keys[ix] >> sh) & 0xFFull);
                if (byt > bsl) {
                    int q = atomicAdd(&s_nwin, 1);
                    wink[q] = keys[ix];
                } else if (byt == bsl) {
                    int q = atomicAdd(&s_neq[cur ^ 1], 1);
                    eqi[cur ^ 1][q] = ix;
                }
            }
            __syncthreads();
            cur ^= 1;
        }
    } else if (np > EQCAP) {
        // ---- fallback (adversarial cnt only): non-destructive argmax ----
        unsigned long long floorkey = 0xFFFFFFFFFFFFFFFFull;
        for (int k = 0; k < selk; k++) {
            unsigned long long best = 0ull;
            for (int m = base + tid; m < end; m += 256) {
                unsigned long long key = mk_key(logit_at(ga, gb, m), m);
                if (key < floorkey && key > best) best = key;
            }
            #pragma unroll
            for (int off = 16; off > 0; off >>= 1) {
                unsigned long long o = __shfl_down_sync(0xFFFFFFFFu, best, off);
                if (o > best) best = o;
            }
            if (lane == 0) red[warp] = best;
            __syncthreads();
            if (tid == 0) {
                unsigned long long bb = red[0];
                #pragma unroll
                for (int w = 1; w < 8; w++) if (red[w] > bb) bb = red[w];
                wink[k] = bb;
                red[0] = bb;
            }
            __syncthreads();
            floorkey = red[0];
            __syncthreads();
        }
    }
    __syncthreads();

    // ---- write staging (pad with tiny distinct keys; real keys >= 2^32) ----
    if (tid < TOPK) {
        unsigned long long key = (tid < selk)
            ? wink[tid]
            : (unsigned long long)(p * TOPK + tid + 1);
        g_pk[b][p * TOPK + tid] = key;
    }
    __syncthreads();

    // ---- last part block for this query does the merge ----
    if (tid == 0) {
        __threadfence();
        s_last = (atomicAdd(&g_qdone[b], 1) == P_PARTS - 1) ? 1 : 0;
    }
    __syncthreads();
    if (!s_last) return;
    __threadfence();   // acquire: other parts' g_pk writes

    unsigned long long mine = g_pk[b][tid];
    keys[tid] = mine;
    __syncthreads();
    int rank = 0;
    #pragma unroll 8
    for (int j = 0; j < P_PARTS * TOPK; j++)
        rank += (keys[j] > mine) ? 1 : 0;
    if (rank < TOPK) {
        sv[rank] = u2f_ord((unsigned int)(mine >> 32));
        si[rank] = (int)(~(unsigned int)(mine & 0xFFFFFFFFull));
    }
    __syncthreads();

    // candidate position -> original row index
    if (tid < TOPK) si[tid] = g_cidx[si[tid]];
    __syncthreads();

    // softmax over the 32 selected logits (order-invariant)
    if (tid < 32) {
        float v = sv[tid];
        float mx = v;
        #pragma unroll
        for (int off = 16; off > 0; off >>= 1)
            mx = fmaxf(mx, __shfl_xor_sync(0xFFFFFFFFu, mx, off));
        float e = expf(v - mx);
        float ssum = e;
        #pragma unroll
        for (int off = 16; off > 0; off >>= 1)
            ssum += __shfl_xor_sync(0xFFFFFFFFu, ssum, off);
        sv[tid] = e / ssum;
    }
    __syncthreads();

    // gather: out[b, d] = sum_k attn[k] * V[idx_k, d]   (tid == d)
    float acc = 0.0f;
    #pragma unroll
    for (int k = 0; k < TOPK; k++)
        acc += sv[k] * Vbank[(size_t)si[k] * DIM + tid];
    out[b * DIM + tid] = acc;
}

// ---------------------------------------------------------------------------
extern "C" void kernel_launch(void* const* d_in, const int* in_sizes, int n_in,
                              void* d_out, int out_size) {
    const float* query = (const float*)d_in[0];
    const float* Kbank = (const float*)d_in[1];
    const float* Vbank = (const float*)d_in[2];
    const float* times = (const float*)d_in[3];
    const float* qtime = (const float*)d_in[4];
    float* out = (float*)d_out;

    int B = in_sizes[0] / DIM;
    int N = in_sizes[3];

    int logits_smem = (DIM * QG + DH * CG) * (int)sizeof(float);  // 64 KB
    cudaFuncSetAttribute(k_logits, cudaFuncAttributeMaxDynamicSharedMemorySize,
                         logits_smem);

    k_pre<<<PRE_BLOCKS, 1024>>>(times, qtime, query, N, B);
    dim3 g2(LX, (B + QG - 1) / QG);       // 444 blocks = 3/SM
    k_logits<<<g2, 128, logits_smem>>>(Kbank, B);
    dim3 g3(P_PARTS, (unsigned)B);
    k_sel<<<g3, 256>>>(Vbank, out, B);
}